// round 3
// baseline (speedup 1.0000x reference)
#include <cuda_runtime.h>
#include <math.h>

typedef unsigned long long u64;

#define TT 10
#define DD 64
#define NL 3
#define WARPS_PER_BLOCK 4
#define PER_WARP_SMEM 15360   // bytes: s_n (5120) + s_h (2560) + s_q (7680)

// ---------- packed f32x2 helpers ----------
__device__ __forceinline__ u64 pk2(float x, float y) {
    u64 r; asm("mov.b64 %0, {%1, %2};" : "=l"(r) : "f"(x), "f"(y)); return r;
}
__device__ __forceinline__ u64 dup1(float x) { return pk2(x, x); }
__device__ __forceinline__ void up2(u64 v, float& x, float& y) {
    asm("mov.b64 {%0, %1}, %2;" : "=f"(x), "=f"(y) : "l"(v));
}
__device__ __forceinline__ u64 ffma2(u64 a, u64 b, u64 c) {
    u64 d; asm("fma.rn.f32x2 %0, %1, %2, %3;" : "=l"(d) : "l"(a), "l"(b), "l"(c)); return d;
}

__device__ __forceinline__ float gelu_exact(float x) {
    return 0.5f * x * (1.0f + erff(x * 0.7071067811865475f));
}

// acc[t] += act[t][:] @ W[:, (c0,c0+1)]   with K = 64.
// w points at W[0][c0] (column pair), row stride ldw (floats).
// act is duplicated-f32x2 format: act[t*lda + d] = (a, a). lda in u64 units.
__device__ __forceinline__ void gemm64(const float* __restrict__ w, int ldw,
                                       const u64* __restrict__ act, int lda,
                                       u64* acc)
{
    #pragma unroll 1
    for (int d = 0; d < 64; d += 4) {
        u64 w0 = *reinterpret_cast<const u64*>(w + (d + 0) * ldw);
        u64 w1 = *reinterpret_cast<const u64*>(w + (d + 1) * ldw);
        u64 w2 = *reinterpret_cast<const u64*>(w + (d + 2) * ldw);
        u64 w3 = *reinterpret_cast<const u64*>(w + (d + 3) * ldw);
        #pragma unroll
        for (int t = 0; t < TT; t++) {
            ulonglong2 a01 = *reinterpret_cast<const ulonglong2*>(act + t * lda + d);
            ulonglong2 a23 = *reinterpret_cast<const ulonglong2*>(act + t * lda + d + 2);
            acc[t] = ffma2(a01.x, w0, acc[t]);
            acc[t] = ffma2(a01.y, w1, acc[t]);
            acc[t] = ffma2(a23.x, w2, acc[t]);
            acc[t] = ffma2(a23.y, w3, acc[t]);
        }
    }
}

// LayerNorm over D=64 (lane owns cols c0, c0+1). Writes duplicated format to s_n.
__device__ __forceinline__ void layernorm_to_dup(const float* __restrict__ s_h,
                                                 const float* __restrict__ g,
                                                 const float* __restrict__ bb,
                                                 u64* __restrict__ s_n, int c0)
{
    float2 gv = *reinterpret_cast<const float2*>(g + c0);
    float2 bv = *reinterpret_cast<const float2*>(bb + c0);
    #pragma unroll
    for (int t = 0; t < TT; t++) {
        float v0 = s_h[t * DD + c0], v1 = s_h[t * DD + c0 + 1];
        float s = v0 + v1, s2 = v0 * v0 + v1 * v1;
        #pragma unroll
        for (int o = 16; o > 0; o >>= 1) {
            s  += __shfl_xor_sync(0xffffffffu, s,  o);
            s2 += __shfl_xor_sync(0xffffffffu, s2, o);
        }
        float m   = s * (1.0f / 64.0f);
        float var = s2 * (1.0f / 64.0f) - m * m;
        float rs  = rsqrtf(var + 1e-5f);
        float n0 = (v0 - m) * rs * gv.x + bv.x;
        float n1 = (v1 - m) * rs * gv.y + bv.y;
        s_n[t * DD + c0]     = dup1(n0);
        s_n[t * DD + c0 + 1] = dup1(n1);
    }
}

extern "C" __global__ void __launch_bounds__(128, 3)
wt49_kernel(const float* __restrict__ x,
            const float* __restrict__ embed_w, const float* __restrict__ embed_b,
            const float* __restrict__ ln1_g,   const float* __restrict__ ln1_b,
            const float* __restrict__ qkv_w,   const float* __restrict__ proj_w,
            const float* __restrict__ ln2_g,   const float* __restrict__ ln2_b,
            const float* __restrict__ ffn_w1,  const float* __restrict__ ffn_b1,
            const float* __restrict__ ffn_w2,  const float* __restrict__ ffn_b2,
            const float* __restrict__ lnf_g,   const float* __restrict__ lnf_b,
            const float* __restrict__ head_w,  const float* __restrict__ head_b,
            float* __restrict__ out, int nB)
{
    extern __shared__ char smem_raw[];
    const int wid = threadIdx.x >> 5;
    const int l   = threadIdx.x & 31;
    const int b   = blockIdx.x * WARPS_PER_BLOCK + wid;
    if (b >= nB) return;                    // whole warp exits together; no block syncs used

    char* wb = smem_raw + wid * PER_WARP_SMEM;
    u64*   s_n   = reinterpret_cast<u64*>(wb);              // [10][64] dup activations
    float* s_h   = reinterpret_cast<float*>(wb + 5120);     // [10][64] residual
    float* s_q   = reinterpret_cast<float*>(wb + 7680);     // [10][192] q|k|v
    u64*   s_z   = reinterpret_cast<u64*>(wb + 7680);       // [10][96] dup y/z (aliases q|k region)
    float* s_att = reinterpret_cast<float*>(wb);            // [400] scores (aliases s_n when free)

    const int c0 = l * 2;
    const unsigned FULL = 0xffffffffu;

    // ---------------- embed: h = x @ We + be ----------------
    {
        float4 xv = make_float4(0.f, 0.f, 0.f, 0.f);
        if (l < TT) xv = *reinterpret_cast<const float4*>(x + (size_t)b * 40 + l * 4);
        u64 e0 = *reinterpret_cast<const u64*>(embed_w + 0 * DD + c0);
        u64 e1 = *reinterpret_cast<const u64*>(embed_w + 1 * DD + c0);
        u64 e2 = *reinterpret_cast<const u64*>(embed_w + 2 * DD + c0);
        u64 e3 = *reinterpret_cast<const u64*>(embed_w + 3 * DD + c0);
        u64 eb = *reinterpret_cast<const u64*>(embed_b + c0);
        #pragma unroll
        for (int t = 0; t < TT; t++) {
            float a0 = __shfl_sync(FULL, xv.x, t);
            float a1 = __shfl_sync(FULL, xv.y, t);
            float a2 = __shfl_sync(FULL, xv.z, t);
            float a3 = __shfl_sync(FULL, xv.w, t);
            u64 acc = eb;
            acc = ffma2(dup1(a0), e0, acc);
            acc = ffma2(dup1(a1), e1, acc);
            acc = ffma2(dup1(a2), e2, acc);
            acc = ffma2(dup1(a3), e3, acc);
            float r0, r1; up2(acc, r0, r1);
            s_h[t * DD + c0] = r0; s_h[t * DD + c0 + 1] = r1;
        }
    }
    __syncwarp();

    // ---------------- transformer layers ----------------
    #pragma unroll 1
    for (int li = 0; li < NL; li++) {
        // LN1 -> s_n (dup)
        layernorm_to_dup(s_h, ln1_g + li * DD, ln1_b + li * DD, s_n, c0);
        __syncwarp();

        // qkv = hn @ Wqkv  (no bias)
        const float* Wq = qkv_w + (size_t)li * (DD * 3 * DD);
        {
            u64 acc[TT];
            #pragma unroll
            for (int t = 0; t < TT; t++) acc[t] = 0ull;
            gemm64(Wq + c0, 192, s_n, DD, acc);
            #pragma unroll
            for (int t = 0; t < TT; t++) { float r0, r1; up2(acc[t], r0, r1);
                s_q[t * 192 + c0] = r0; s_q[t * 192 + c0 + 1] = r1; }
        }
        {
            u64 acc[TT];
            #pragma unroll
            for (int t = 0; t < TT; t++) acc[t] = 0ull;
            gemm64(Wq + 64 + c0, 192, s_n, DD, acc);
            #pragma unroll
            for (int t = 0; t < TT; t++) { float r0, r1; up2(acc[t], r0, r1);
                s_q[t * 192 + 64 + c0] = r0; s_q[t * 192 + 64 + c0 + 1] = r1; }
        }
        {
            u64 acc[TT];
            #pragma unroll
            for (int t = 0; t < TT; t++) acc[t] = 0ull;
            gemm64(Wq + 128 + c0, 192, s_n, DD, acc);
            #pragma unroll
            for (int t = 0; t < TT; t++) { float r0, r1; up2(acc[t], r0, r1);
                s_q[t * 192 + 128 + c0] = r0; s_q[t * 192 + 128 + c0 + 1] = r1; }
        }
        __syncwarp();

        // attention scores: att[h][tq][tk] = 0.25 * dot(q,k)  (s_n region is free now)
        #pragma unroll 1
        for (int idx = l; idx < 400; idx += 32) {
            int hh = idx / 100;
            int r  = idx % 100;
            int tq = r / 10, tk = r % 10;
            const float* qp = s_q + tq * 192 + hh * 16;
            const float* kp = s_q + tk * 192 + 64 + hh * 16;
            float dot = 0.f;
            #pragma unroll
            for (int j = 0; j < 16; j += 4) {
                float4 q4 = *reinterpret_cast<const float4*>(qp + j);
                float4 k4 = *reinterpret_cast<const float4*>(kp + j);
                dot += q4.x * k4.x + q4.y * k4.y + q4.z * k4.z + q4.w * k4.w;
            }
            s_att[idx] = dot * 0.25f;
        }
        __syncwarp();

        // causal softmax per row
        #pragma unroll 1
        for (int r = l; r < 40; r += 32) {
            int tq = r % 10;
            float* row = s_att + r * 10;
            float m = row[0];
            for (int k = 1; k <= tq; k++) m = fmaxf(m, row[k]);
            float ssum = 0.f;
            for (int k = 0; k <= tq; k++) { float e = expf(row[k] - m); row[k] = e; ssum += e; }
            float inv = 1.f / ssum;
            #pragma unroll
            for (int k = 0; k < TT; k++) row[k] = (k <= tq) ? row[k] * inv : 0.f;
        }
        __syncwarp();

        // y = att @ v  -> store duplicated into s_z (overwrites q|k region, v region untouched)
        {
            const int hh = l >> 3;   // head of column pair (c0, c0+1)
            u64 acc[TT];
            #pragma unroll
            for (int t = 0; t < TT; t++) acc[t] = 0ull;
            #pragma unroll
            for (int t = 0; t < TT; t++) {
                #pragma unroll
                for (int tk = 0; tk < TT; tk++) {
                    float a = s_att[(hh * 10 + t) * 10 + tk];
                    u64 v2 = *reinterpret_cast<const u64*>(s_q + tk * 192 + 128 + c0);
                    acc[t] = ffma2(dup1(a), v2, acc[t]);
                }
            }
            #pragma unroll
            for (int t = 0; t < TT; t++) { float r0, r1; up2(acc[t], r0, r1);
                s_z[t * 96 + c0] = dup1(r0); s_z[t * 96 + c0 + 1] = dup1(r1); }
        }
        __syncwarp();

        // h += y @ Wproj
        {
            u64 acc[TT];
            #pragma unroll
            for (int t = 0; t < TT; t++) acc[t] = 0ull;
            gemm64(proj_w + (size_t)li * DD * DD + c0, DD, s_z, 96, acc);
            #pragma unroll
            for (int t = 0; t < TT; t++) { float r0, r1; up2(acc[t], r0, r1);
                s_h[t * DD + c0] += r0; s_h[t * DD + c0 + 1] += r1; }
        }
        __syncwarp();

        // LN2 -> s_n (dup)
        layernorm_to_dup(s_h, ln2_g + li * DD, ln2_b + li * DD, s_n, c0);
        __syncwarp();

        // FFN: h += gelu(hn @ W1 + b1) @ W2 + b2   (4 column chunks of 64)
        {
            const float* W1 = ffn_w1 + (size_t)li * DD * 256;
            const float* W2 = ffn_w2 + (size_t)li * 256 * DD;
            const float* B1 = ffn_b1 + li * 256;
            u64 acch[TT];
            u64 b2v = *reinterpret_cast<const u64*>(ffn_b2 + li * DD + c0);
            #pragma unroll
            for (int t = 0; t < TT; t++) acch[t] = b2v;

            #pragma unroll 1
            for (int cc = 0; cc < 4; cc++) {
                u64 accz[TT];
                u64 b1v = *reinterpret_cast<const u64*>(B1 + cc * 64 + c0);
                #pragma unroll
                for (int t = 0; t < TT; t++) accz[t] = b1v;
                gemm64(W1 + cc * 64 + c0, 256, s_n, DD, accz);
                #pragma unroll
                for (int t = 0; t < TT; t++) {
                    float z0, z1; up2(accz[t], z0, z1);
                    z0 = gelu_exact(z0); z1 = gelu_exact(z1);
                    s_z[t * 96 + c0] = dup1(z0); s_z[t * 96 + c0 + 1] = dup1(z1);
                }
                __syncwarp();
                gemm64(W2 + (size_t)(cc * 64) * DD + c0, DD, s_z, 96, acch);
                __syncwarp();
            }
            #pragma unroll
            for (int t = 0; t < TT; t++) { float r0, r1; up2(acch[t], r0, r1);
                s_h[t * DD + c0] += r0; s_h[t * DD + c0 + 1] += r1; }
        }
        __syncwarp();
    }

    // ---------------- final LN (t=9 only) + head ----------------
    {
        float v0 = s_h[9 * DD + c0], v1 = s_h[9 * DD + c0 + 1];
        float s = v0 + v1, s2 = v0 * v0 + v1 * v1;
        #pragma unroll
        for (int o = 16; o > 0; o >>= 1) {
            s  += __shfl_xor_sync(FULL, s,  o);
            s2 += __shfl_xor_sync(FULL, s2, o);
        }
        float m   = s * (1.0f / 64.0f);
        float var = s2 * (1.0f / 64.0f) - m * m;
        float rs  = rsqrtf(var + 1e-5f);
        float2 gv = *reinterpret_cast<const float2*>(lnf_g + c0);
        float2 bv = *reinterpret_cast<const float2*>(lnf_b + c0);
        s_q[c0]     = (v0 - m) * rs * gv.x + bv.x;
        s_q[c0 + 1] = (v1 - m) * rs * gv.y + bv.y;
    }
    __syncwarp();
    if (l < 10) {
        float acc = head_b[l];
        #pragma unroll 1
        for (int d = 0; d < DD; d++) acc = fmaf(s_q[d], head_w[d * 10 + l], acc);
        out[(size_t)b * 10 + l] = acc;
    }
}

extern "C" void kernel_launch(void* const* d_in, const int* in_sizes, int n_in,
                              void* d_out, int out_size)
{
    const float* x       = (const float*)d_in[0];
    const float* embed_w = (const float*)d_in[1];
    const float* embed_b = (const float*)d_in[2];
    const float* ln1_g   = (const float*)d_in[3];
    const float* ln1_b   = (const float*)d_in[4];
    const float* qkv_w   = (const float*)d_in[5];
    const float* proj_w  = (const float*)d_in[6];
    const float* ln2_g   = (const float*)d_in[7];
    const float* ln2_b   = (const float*)d_in[8];
    const float* ffn_w1  = (const float*)d_in[9];
    const float* ffn_b1  = (const float*)d_in[10];
    const float* ffn_w2  = (const float*)d_in[11];
    const float* ffn_w2b = (const float*)d_in[12];
    const float* lnf_g   = (const float*)d_in[13];
    const float* lnf_b   = (const float*)d_in[14];
    const float* head_w  = (const float*)d_in[15];
    const float* head_b  = (const float*)d_in[16];
    float* out = (float*)d_out;

    int nB = in_sizes[0] / 40;                       // [B, T=10, 4]
    int grid = (nB + WARPS_PER_BLOCK - 1) / WARPS_PER_BLOCK;
    size_t smem = (size_t)WARPS_PER_BLOCK * PER_WARP_SMEM;   // 61440 B

    // >48KB dynamic smem requires opt-in (idempotent; safe under graph capture).
    cudaFuncSetAttribute(wt49_kernel, cudaFuncAttributeMaxDynamicSharedMemorySize, (int)smem);

    wt49_kernel<<<grid, 128, smem>>>(x, embed_w, embed_b, ln1_g, ln1_b, qkv_w, proj_w,
                                     ln2_g, ln2_b, ffn_w1, ffn_b1, ffn_w2, ffn_w2b,
                                     lnf_g, lnf_b, head_w, head_b, out, nB);
}

// round 4
// speedup vs baseline: 1.2034x; 1.2034x over previous
#include <cuda_runtime.h>
#include <math.h>

typedef unsigned long long u64;

#define TT 10
#define DD 64
#define NL 3
#define WPB 7
#define PER_WARP_SMEM 15360   // s_h 2560 | s_aT 2560 | s_zT 2560 | s_q 7680

// ---------- packed f32x2 helpers ----------
__device__ __forceinline__ u64 pk2(float x, float y) {
    u64 r; asm("mov.b64 %0, {%1, %2};" : "=l"(r) : "f"(x), "f"(y)); return r;
}
__device__ __forceinline__ u64 dup1(float x) { return pk2(x, x); }
__device__ __forceinline__ void up2(u64 v, float& x, float& y) {
    asm("mov.b64 {%0, %1}, %2;" : "=f"(x), "=f"(y) : "l"(v));
}
__device__ __forceinline__ u64 ffma2(u64 a, u64 b, u64 c) {
    u64 d; asm("fma.rn.f32x2 %0, %1, %2, %3;" : "=l"(d) : "l"(a), "l"(b), "l"(c)); return d;
}
__device__ __forceinline__ float gelu_exact(float x) {
    return 0.5f * x * (1.0f + erff(x * 0.7071067811865475f));
}

// acc0[tp] = (out[2tp][c0], out[2tp+1][c0]),  acc1[tp] = same for c0+1.
// aT: transposed activations [64][10] floats, contiguous (16B-aligned base).
// w points at W[0][c0]; ldw = row stride in floats (compile-time constant at call sites).
__device__ __forceinline__ void gemm64_tp(const float* __restrict__ w, const int ldw,
                                          const float* __restrict__ aT,
                                          u64* __restrict__ acc0, u64* __restrict__ acc1)
{
    #pragma unroll 2
    for (int k = 0; k < 64; k += 2) {
        // 20 floats = rows k, k+1 of aT, as 5x LDS.128 (all 16B-aligned for even k)
        const ulonglong2* ap = reinterpret_cast<const ulonglong2*>(aT + k * 10);
        ulonglong2 q0 = ap[0];   // a[k][0..3]
        ulonglong2 q1 = ap[1];   // a[k][4..7]
        ulonglong2 q2 = ap[2];   // a[k][8..9], a[k+1][0..1]
        ulonglong2 q3 = ap[3];   // a[k+1][2..5]
        ulonglong2 q4 = ap[4];   // a[k+1][6..9]
        u64 wA = *reinterpret_cast<const u64*>(w + (k    ) * ldw);
        u64 wB = *reinterpret_cast<const u64*>(w + (k + 1) * ldw);
        float wa0, wa1, wb0, wb1;
        up2(wA, wa0, wa1); up2(wB, wb0, wb1);
        u64 da0 = dup1(wa0), da1 = dup1(wa1);
        u64 db0 = dup1(wb0), db1 = dup1(wb1);
        // row k
        acc0[0] = ffma2(q0.x, da0, acc0[0]);  acc1[0] = ffma2(q0.x, da1, acc1[0]);
        acc0[1] = ffma2(q0.y, da0, acc0[1]);  acc1[1] = ffma2(q0.y, da1, acc1[1]);
        acc0[2] = ffma2(q1.x, da0, acc0[2]);  acc1[2] = ffma2(q1.x, da1, acc1[2]);
        acc0[3] = ffma2(q1.y, da0, acc0[3]);  acc1[3] = ffma2(q1.y, da1, acc1[3]);
        acc0[4] = ffma2(q2.x, da0, acc0[4]);  acc1[4] = ffma2(q2.x, da1, acc1[4]);
        // row k+1
        acc0[0] = ffma2(q2.y, db0, acc0[0]);  acc1[0] = ffma2(q2.y, db1, acc1[0]);
        acc0[1] = ffma2(q3.x, db0, acc0[1]);  acc1[1] = ffma2(q3.x, db1, acc1[1]);
        acc0[2] = ffma2(q3.y, db0, acc0[2]);  acc1[2] = ffma2(q3.y, db1, acc1[2]);
        acc0[3] = ffma2(q4.x, db0, acc0[3]);  acc1[3] = ffma2(q4.x, db1, acc1[3]);
        acc0[4] = ffma2(q4.y, db0, acc0[4]);  acc1[4] = ffma2(q4.y, db1, acc1[4]);
    }
}

// LayerNorm over D=64; lane owns cols c0,c0+1. Writes TRANSPOSED plain floats to aT.
__device__ __forceinline__ void layernorm_to_T(const float* __restrict__ s_h,
                                               const float* __restrict__ g,
                                               const float* __restrict__ bb,
                                               float* __restrict__ aT, int c0)
{
    float2 gv = *reinterpret_cast<const float2*>(g + c0);
    float2 bv = *reinterpret_cast<const float2*>(bb + c0);
    #pragma unroll
    for (int t = 0; t < TT; t++) {
        float v0 = s_h[t * DD + c0], v1 = s_h[t * DD + c0 + 1];
        float s = v0 + v1, s2 = v0 * v0 + v1 * v1;
        #pragma unroll
        for (int o = 16; o > 0; o >>= 1) {
            s  += __shfl_xor_sync(0xffffffffu, s,  o);
            s2 += __shfl_xor_sync(0xffffffffu, s2, o);
        }
        float m   = s * (1.0f / 64.0f);
        float var = s2 * (1.0f / 64.0f) - m * m;
        float rs  = rsqrtf(var + 1e-5f);
        aT[c0 * TT + t]       = (v0 - m) * rs * gv.x + bv.x;
        aT[(c0 + 1) * TT + t] = (v1 - m) * rs * gv.y + bv.y;
    }
}

extern "C" __global__ void __launch_bounds__(WPB * 32, 2)
wt49_kernel(const float* __restrict__ x,
            const float* __restrict__ embed_w, const float* __restrict__ embed_b,
            const float* __restrict__ ln1_g,   const float* __restrict__ ln1_b,
            const float* __restrict__ qkv_w,   const float* __restrict__ proj_w,
            const float* __restrict__ ln2_g,   const float* __restrict__ ln2_b,
            const float* __restrict__ ffn_w1,  const float* __restrict__ ffn_b1,
            const float* __restrict__ ffn_w2,  const float* __restrict__ ffn_b2,
            const float* __restrict__ lnf_g,   const float* __restrict__ lnf_b,
            const float* __restrict__ head_w,  const float* __restrict__ head_b,
            float* __restrict__ out, int nB)
{
    extern __shared__ char smem_raw[];
    const int wid = threadIdx.x >> 5;
    const int l   = threadIdx.x & 31;
    const int b   = blockIdx.x * WPB + wid;
    if (b >= nB) return;                 // warp-uniform exit; no block-level syncs used

    char* wb = smem_raw + wid * PER_WARP_SMEM;
    float* s_h   = reinterpret_cast<float*>(wb);            // [10][64] residual
    float* s_aT  = reinterpret_cast<float*>(wb + 2560);     // [64][10] transposed acts (aliases scores / y_T)
    float* s_zT  = reinterpret_cast<float*>(wb + 5120);     // [64][10] transposed z (aliases att_T)
    float* s_q   = reinterpret_cast<float*>(wb + 7680);     // [10][192] q|k|v
    float* s_att = s_aT;                                     // [400] raw scores
    float* s_atT = s_zT;                                     // [4][10][10] att transposed (tk-major)

    const int c0 = l * 2;
    const unsigned FULL = 0xffffffffu;

    // ---------------- embed: h = x @ We + be ----------------
    {
        float4 xv = make_float4(0.f, 0.f, 0.f, 0.f);
        if (l < TT) xv = *reinterpret_cast<const float4*>(x + (size_t)b * 40 + l * 4);
        u64 e0 = *reinterpret_cast<const u64*>(embed_w + 0 * DD + c0);
        u64 e1 = *reinterpret_cast<const u64*>(embed_w + 1 * DD + c0);
        u64 e2 = *reinterpret_cast<const u64*>(embed_w + 2 * DD + c0);
        u64 e3 = *reinterpret_cast<const u64*>(embed_w + 3 * DD + c0);
        u64 eb = *reinterpret_cast<const u64*>(embed_b + c0);
        #pragma unroll
        for (int t = 0; t < TT; t++) {
            float a0 = __shfl_sync(FULL, xv.x, t);
            float a1 = __shfl_sync(FULL, xv.y, t);
            float a2 = __shfl_sync(FULL, xv.z, t);
            float a3 = __shfl_sync(FULL, xv.w, t);
            u64 acc = eb;
            acc = ffma2(dup1(a0), e0, acc);
            acc = ffma2(dup1(a1), e1, acc);
            acc = ffma2(dup1(a2), e2, acc);
            acc = ffma2(dup1(a3), e3, acc);
            float r0, r1; up2(acc, r0, r1);
            s_h[t * DD + c0] = r0; s_h[t * DD + c0 + 1] = r1;
        }
    }
    __syncwarp();

    // ---------------- transformer layers ----------------
    #pragma unroll 1
    for (int li = 0; li < NL; li++) {
        // LN1 -> s_aT (transposed)
        layernorm_to_T(s_h, ln1_g + li * DD, ln1_b + li * DD, s_aT, c0);
        __syncwarp();

        // qkv = hn @ Wqkv
        const float* Wq = qkv_w + (size_t)li * (DD * 3 * DD);
        #pragma unroll 1
        for (int part = 0; part < 3; part++) {
            u64 a0[5], a1[5];
            #pragma unroll
            for (int tp = 0; tp < 5; tp++) { a0[tp] = 0ull; a1[tp] = 0ull; }
            gemm64_tp(Wq + part * 64 + c0, 192, s_aT, a0, a1);
            #pragma unroll
            for (int tp = 0; tp < 5; tp++) {
                float x0, x1, y0, y1;
                up2(a0[tp], x0, x1); up2(a1[tp], y0, y1);
                int c = part * 64 + c0;
                s_q[(2 * tp    ) * 192 + c]     = x0;
                s_q[(2 * tp + 1) * 192 + c]     = x1;
                s_q[(2 * tp    ) * 192 + c + 1] = y0;
                s_q[(2 * tp + 1) * 192 + c + 1] = y1;
            }
        }
        __syncwarp();

        // scores: att[h][tq][tk] = 0.25 * dot(q,k)   (s_aT region free now)
        #pragma unroll 1
        for (int idx = l; idx < 400; idx += 32) {
            int hh = idx / 100;
            int r  = idx % 100;
            int tq = r / 10, tk = r % 10;
            const float* qp = s_q + tq * 192 + hh * 16;
            const float* kp = s_q + tk * 192 + 64 + hh * 16;
            float dot = 0.f;
            #pragma unroll
            for (int j = 0; j < 16; j += 4) {
                float4 q4 = *reinterpret_cast<const float4*>(qp + j);
                float4 k4 = *reinterpret_cast<const float4*>(kp + j);
                dot += q4.x * k4.x + q4.y * k4.y + q4.z * k4.z + q4.w * k4.w;
            }
            s_att[idx] = dot * 0.25f;
        }
        __syncwarp();

        // causal softmax per (h,tq) row; write TRANSPOSED into s_atT[h][tk][tq]
        #pragma unroll 1
        for (int r = l; r < 40; r += 32) {
            int hh = r / 10, tq = r % 10;
            const float* row = s_att + r * 10;
            float v[TT];
            #pragma unroll
            for (int k = 0; k < TT; k++) v[k] = row[k];
            float m = v[0];
            for (int k = 1; k <= tq; k++) m = fmaxf(m, v[k]);
            float ssum = 0.f;
            for (int k = 0; k <= tq; k++) { float e = expf(v[k] - m); v[k] = e; ssum += e; }
            float inv = 1.f / ssum;
            #pragma unroll
            for (int k = 0; k < TT; k++)
                s_atT[hh * 100 + k * 10 + tq] = (k <= tq) ? v[k] * inv : 0.f;
        }
        __syncwarp();

        // y = att @ v  (t-pair over query index), write y_T into s_aT
        {
            const int hh = l >> 3;
            const float* at = s_atT + hh * 100;      // [tk][tq] 10x10, 16B-aligned
            u64 y0[5], y1[5];
            #pragma unroll
            for (int tp = 0; tp < 5; tp++) { y0[tp] = 0ull; y1[tp] = 0ull; }
            #pragma unroll
            for (int tk = 0; tk < TT; tk += 2) {
                const ulonglong2* ap = reinterpret_cast<const ulonglong2*>(at + tk * 10);
                ulonglong2 q0 = ap[0], q1 = ap[1], q2 = ap[2], q3 = ap[3], q4 = ap[4];
                u64 vA = *reinterpret_cast<const u64*>(s_q + (tk    ) * 192 + 128 + c0);
                u64 vB = *reinterpret_cast<const u64*>(s_q + (tk + 1) * 192 + 128 + c0);
                float va0, va1, vb0, vb1;
                up2(vA, va0, va1); up2(vB, vb0, vb1);
                u64 da0 = dup1(va0), da1 = dup1(va1);
                u64 db0 = dup1(vb0), db1 = dup1(vb1);
                y0[0] = ffma2(q0.x, da0, y0[0]);  y1[0] = ffma2(q0.x, da1, y1[0]);
                y0[1] = ffma2(q0.y, da0, y0[1]);  y1[1] = ffma2(q0.y, da1, y1[1]);
                y0[2] = ffma2(q1.x, da0, y0[2]);  y1[2] = ffma2(q1.x, da1, y1[2]);
                y0[3] = ffma2(q1.y, da0, y0[3]);  y1[3] = ffma2(q1.y, da1, y1[3]);
                y0[4] = ffma2(q2.x, da0, y0[4]);  y1[4] = ffma2(q2.x, da1, y1[4]);
                y0[0] = ffma2(q2.y, db0, y0[0]);  y1[0] = ffma2(q2.y, db1, y1[0]);
                y0[1] = ffma2(q3.x, db0, y0[1]);  y1[1] = ffma2(q3.x, db1, y1[1]);
                y0[2] = ffma2(q3.y, db0, y0[2]);  y1[2] = ffma2(q3.y, db1, y1[2]);
                y0[3] = ffma2(q4.x, db0, y0[3]);  y1[3] = ffma2(q4.x, db1, y1[3]);
                y0[4] = ffma2(q4.y, db0, y0[4]);  y1[4] = ffma2(q4.y, db1, y1[4]);
            }
            #pragma unroll
            for (int tp = 0; tp < 5; tp++) {
                float x0, x1, z0, z1;
                up2(y0[tp], x0, x1); up2(y1[tp], z0, z1);
                s_aT[c0 * TT + 2 * tp]           = x0;
                s_aT[c0 * TT + 2 * tp + 1]       = x1;
                s_aT[(c0 + 1) * TT + 2 * tp]     = z0;
                s_aT[(c0 + 1) * TT + 2 * tp + 1] = z1;
            }
        }
        __syncwarp();

        // h += y @ Wproj
        {
            u64 p0[5], p1[5];
            #pragma unroll
            for (int tp = 0; tp < 5; tp++) { p0[tp] = 0ull; p1[tp] = 0ull; }
            gemm64_tp(proj_w + (size_t)li * DD * DD + c0, 64, s_aT, p0, p1);
            #pragma unroll
            for (int tp = 0; tp < 5; tp++) {
                float x0, x1, y0, y1;
                up2(p0[tp], x0, x1); up2(p1[tp], y0, y1);
                s_h[(2 * tp    ) * DD + c0]     += x0;
                s_h[(2 * tp + 1) * DD + c0]     += x1;
                s_h[(2 * tp    ) * DD + c0 + 1] += y0;
                s_h[(2 * tp + 1) * DD + c0 + 1] += y1;
            }
        }
        __syncwarp();

        // LN2 -> s_aT
        layernorm_to_T(s_h, ln2_g + li * DD, ln2_b + li * DD, s_aT, c0);
        __syncwarp();

        // FFN: h += gelu(hn @ W1 + b1) @ W2 + b2   (4 chunks of 64 hidden cols)
        {
            const float* W1 = ffn_w1 + (size_t)li * DD * 256;
            const float* W2 = ffn_w2 + (size_t)li * 256 * DD;
            const float* B1 = ffn_b1 + li * 256;
            u64 h0[5], h1[5];
            {
                u64 b2v = *reinterpret_cast<const u64*>(ffn_b2 + li * DD + c0);
                float b2l, b2h; up2(b2v, b2l, b2h);
                u64 d0 = dup1(b2l), d1 = dup1(b2h);
                #pragma unroll
                for (int tp = 0; tp < 5; tp++) { h0[tp] = d0; h1[tp] = d1; }
            }
            #pragma unroll 1
            for (int cc = 0; cc < 4; cc++) {
                u64 z0[5], z1[5];
                {
                    u64 b1v = *reinterpret_cast<const u64*>(B1 + cc * 64 + c0);
                    float bl, bh; up2(b1v, bl, bh);
                    u64 d0 = dup1(bl), d1 = dup1(bh);
                    #pragma unroll
                    for (int tp = 0; tp < 5; tp++) { z0[tp] = d0; z1[tp] = d1; }
                }
                gemm64_tp(W1 + cc * 64 + c0, 256, s_aT, z0, z1);
                #pragma unroll
                for (int tp = 0; tp < 5; tp++) {
                    float x0, x1, y0, y1;
                    up2(z0[tp], x0, x1); up2(z1[tp], y0, y1);
                    s_zT[c0 * TT + 2 * tp]           = gelu_exact(x0);
                    s_zT[c0 * TT + 2 * tp + 1]       = gelu_exact(x1);
                    s_zT[(c0 + 1) * TT + 2 * tp]     = gelu_exact(y0);
                    s_zT[(c0 + 1) * TT + 2 * tp + 1] = gelu_exact(y1);
                }
                __syncwarp();
                gemm64_tp(W2 + (size_t)(cc * 64) * DD + c0, 64, s_zT, h0, h1);
                __syncwarp();
            }
            #pragma unroll
            for (int tp = 0; tp < 5; tp++) {
                float x0, x1, y0, y1;
                up2(h0[tp], x0, x1); up2(h1[tp], y0, y1);
                s_h[(2 * tp    ) * DD + c0]     += x0;
                s_h[(2 * tp + 1) * DD + c0]     += x1;
                s_h[(2 * tp    ) * DD + c0 + 1] += y0;
                s_h[(2 * tp + 1) * DD + c0 + 1] += y1;
            }
        }
        __syncwarp();
    }

    // ---------------- final LN (t=9 only) + head ----------------
    {
        float v0 = s_h[9 * DD + c0], v1 = s_h[9 * DD + c0 + 1];
        float s = v0 + v1, s2 = v0 * v0 + v1 * v1;
        #pragma unroll
        for (int o = 16; o > 0; o >>= 1) {
            s  += __shfl_xor_sync(FULL, s,  o);
            s2 += __shfl_xor_sync(FULL, s2, o);
        }
        float m   = s * (1.0f / 64.0f);
        float var = s2 * (1.0f / 64.0f) - m * m;
        float rs  = rsqrtf(var + 1e-5f);
        float2 gv = *reinterpret_cast<const float2*>(lnf_g + c0);
        float2 bv = *reinterpret_cast<const float2*>(lnf_b + c0);
        s_q[c0]     = (v0 - m) * rs * gv.x + bv.x;
        s_q[c0 + 1] = (v1 - m) * rs * gv.y + bv.y;
    }
    __syncwarp();
    if (l < 10) {
        float acc = head_b[l];
        #pragma unroll 1
        for (int d = 0; d < DD; d++) acc = fmaf(s_q[d], head_w[d * 10 + l], acc);
        out[(size_t)b * 10 + l] = acc;
    }
}

extern "C" void kernel_launch(void* const* d_in, const int* in_sizes, int n_in,
                              void* d_out, int out_size)
{
    const float* x       = (const float*)d_in[0];
    const float* embed_w = (const float*)d_in[1];
    const float* embed_b = (const float*)d_in[2];
    const float* ln1_g   = (const float*)d_in[3];
    const float* ln1_b   = (const float*)d_in[4];
    const float* qkv_w   = (const float*)d_in[5];
    const float* proj_w  = (const float*)d_in[6];
    const float* ln2_g   = (const float*)d_in[7];
    const float* ln2_b   = (const float*)d_in[8];
    const float* ffn_w1  = (const float*)d_in[9];
    const float* ffn_b1  = (const float*)d_in[10];
    const float* ffn_w2  = (const float*)d_in[11];
    const float* ffn_b2  = (const float*)d_in[12];
    const float* lnf_g   = (const float*)d_in[13];
    const float* lnf_b   = (const float*)d_in[14];
    const float* head_w  = (const float*)d_in[15];
    const float* head_b  = (const float*)d_in[16];
    float* out = (float*)d_out;

    int nB = in_sizes[0] / 40;                        // [B, T=10, 4]
    int grid = (nB + WPB - 1) / WPB;
    size_t smem = (size_t)WPB * PER_WARP_SMEM;        // 107520 B -> 2 blocks/SM

    cudaFuncSetAttribute(wt49_kernel, cudaFuncAttributeMaxDynamicSharedMemorySize, (int)smem);

    wt49_kernel<<<grid, WPB * 32, smem>>>(x, embed_w, embed_b, ln1_g, ln1_b, qkv_w, proj_w,
                                          ln2_g, ln2_b, ffn_w1, ffn_b1, ffn_w2, ffn_b2,
                                          lnf_g, lnf_b, head_w, head_b, out, nB);
}

// round 7
// speedup vs baseline: 1.3578x; 1.1283x over previous
#include <cuda_runtime.h>
#include <math.h>

typedef unsigned long long u64;

#define TT 10
#define DD 64
#define NL 3
#define WPB 8
// per-warp smem layout (bytes):
//   s_h   @0     [10][64] f32 residual                       2560
//   s_aT  @2560  padded transposed acts (2x324 floats)       2592
//   s_zT  @5152  padded transposed z / raw attT              2592
//   s_qk  @7744  [10][128] f32  q|k                          5120
#define S_AT  2560
#define S_ZT  5152
#define S_QK  7744
#define PER_WARP_SMEM 12864
#define ATH 324   // half-stride of padded act buffers, in floats (32*10 + 4 pad)

// ---------- packed f32x2 helpers ----------
__device__ __forceinline__ u64 pk2(float x, float y) {
    u64 r; asm("mov.b64 %0, {%1, %2};" : "=l"(r) : "f"(x), "f"(y)); return r;
}
__device__ __forceinline__ u64 dup1(float x) { return pk2(x, x); }
__device__ __forceinline__ void up2(u64 v, float& x, float& y) {
    asm("mov.b64 {%0, %1}, %2;" : "=f"(x), "=f"(y) : "l"(v));
}
__device__ __forceinline__ u64 ffma2(u64 a, u64 b, u64 c) {
    u64 d; asm("fma.rn.f32x2 %0, %1, %2, %3;" : "=l"(d) : "l"(a), "l"(b), "l"(c)); return d;
}
__device__ __forceinline__ u64 add2(u64 a, u64 b) {
    u64 c; asm("add.rn.f32x2 %0, %1, %2;" : "=l"(c) : "l"(a), "l"(b)); return c;
}
__device__ __forceinline__ float gelu_exact(float x) {
    return 0.5f * x * (1.0f + erff(x * 0.7071067811865475f));
}
// padded transposed-act offset for feature column c (floats)
__device__ __forceinline__ int at_off(int c) {
    return ((c >> 5) * ATH) + ((c & 31) * 10);
}

// ---------- split-K C=4 gemm ----------
// Lane computes partial sums for output cols cb..cb+3 over its k-half.
// acc[j][tp] = f32x2 partial (out[2tp][cb+j], out[2tp+1][cb+j]).
// aT: padded transposed acts (half stride ATH floats). w: W[0][0], row stride ldw.
template<int KK>
__device__ __forceinline__ void gemm_sk(const float* __restrict__ w, const int ldw,
                                        const float* __restrict__ aT,
                                        const int half, const int cb, u64 acc[4][5])
{
    const float* a  = aT + half * ATH;
    const float* wp = w + (half * (KK / 2)) * ldw + cb;
    #pragma unroll 2
    for (int kk = 0; kk < KK / 2; kk += 2) {
        const ulonglong2* ap = reinterpret_cast<const ulonglong2*>(a + kk * 10);
        ulonglong2 p0 = ap[0], p1 = ap[1], p2 = ap[2], p3 = ap[3], p4 = ap[4];
        float4 w0 = *reinterpret_cast<const float4*>(wp + kk * ldw);
        float4 w1 = *reinterpret_cast<const float4*>(wp + (kk + 1) * ldw);
        u64 d0[4] = { dup1(w0.x), dup1(w0.y), dup1(w0.z), dup1(w0.w) };
        u64 d1[4] = { dup1(w1.x), dup1(w1.y), dup1(w1.z), dup1(w1.w) };
        u64 avA[5] = { p0.x, p0.y, p1.x, p1.y, p2.x };   // row kk, t-pairs 0..4
        u64 avB[5] = { p2.y, p3.x, p3.y, p4.x, p4.y };   // row kk+1
        #pragma unroll
        for (int tp = 0; tp < 5; tp++)
            #pragma unroll
            for (int j = 0; j < 4; j++)
                acc[j][tp] = ffma2(avA[tp], d0[j], acc[j][tp]);
        #pragma unroll
        for (int tp = 0; tp < 5; tp++)
            #pragma unroll
            for (int j = 0; j < 4; j++)
                acc[j][tp] = ffma2(avB[tp], d1[j], acc[j][tp]);
    }
}

__device__ __forceinline__ void reduce_sk(u64 acc[4][5]) {
    #pragma unroll
    for (int j = 0; j < 4; j++)
        #pragma unroll
        for (int tp = 0; tp < 5; tp++) {
            u64 o = __shfl_xor_sync(0xffffffffu, acc[j][tp], 16);
            acc[j][tp] = add2(acc[j][tp], o);
        }
}

__device__ __forceinline__ void zero_acc(u64 acc[4][5]) {
    #pragma unroll
    for (int j = 0; j < 4; j++)
        #pragma unroll
        for (int tp = 0; tp < 5; tp++) acc[j][tp] = 0ull;
}

// store reduced acc into row-major dst [t][col], stride ldd; tp split by half parity
__device__ __forceinline__ void store_rows(float* __restrict__ dst, const int ldd,
                                           u64 acc[4][5], const int half, const int cb)
{
    #pragma unroll
    for (int tp = 0; tp < 5; tp++) if ((tp & 1) == half) {
        float l0,h0,l1,h1,l2,h2,l3,h3;
        up2(acc[0][tp], l0, h0); up2(acc[1][tp], l1, h1);
        up2(acc[2][tp], l2, h2); up2(acc[3][tp], l3, h3);
        *reinterpret_cast<float4*>(dst + (2*tp    ) * ldd + cb) = make_float4(l0,l1,l2,l3);
        *reinterpret_cast<float4*>(dst + (2*tp + 1) * ldd + cb) = make_float4(h0,h1,h2,h3);
    }
}

// h[t][cb..cb+3] += acc  (read-modify-write, tp split by half parity)
__device__ __forceinline__ void rmw_h(float* __restrict__ s_h, u64 acc[4][5],
                                      const int half, const int cb)
{
    #pragma unroll
    for (int tp = 0; tp < 5; tp++) if ((tp & 1) == half) {
        float l0,h0,l1,h1,l2,h2,l3,h3;
        up2(acc[0][tp], l0, h0); up2(acc[1][tp], l1, h1);
        up2(acc[2][tp], l2, h2); up2(acc[3][tp], l3, h3);
        float4* p0 = reinterpret_cast<float4*>(s_h + (2*tp) * DD + cb);
        float4 v0 = *p0; v0.x += l0; v0.y += l1; v0.z += l2; v0.w += l3; *p0 = v0;
        float4* p1 = reinterpret_cast<float4*>(s_h + (2*tp + 1) * DD + cb);
        float4 v1 = *p1; v1.x += h0; v1.y += h1; v1.z += h2; v1.w += h3; *p1 = v1;
    }
}

// LayerNorm over D=64 from s_h; lane handles cols c0=2l, c0+1; writes padded transposed aT.
__device__ __forceinline__ void layernorm_T(const float* __restrict__ s_h,
                                            const float* __restrict__ g,
                                            const float* __restrict__ bb,
                                            float* __restrict__ aT, const int c0)
{
    float2 gv = *reinterpret_cast<const float2*>(g + c0);
    float2 bv = *reinterpret_cast<const float2*>(bb + c0);
    const int o0 = at_off(c0);
    #pragma unroll
    for (int t = 0; t < TT; t++) {
        float v0 = s_h[t * DD + c0], v1 = s_h[t * DD + c0 + 1];
        float s = v0 + v1, s2 = v0 * v0 + v1 * v1;
        #pragma unroll
        for (int o = 16; o > 0; o >>= 1) {
            s  += __shfl_xor_sync(0xffffffffu, s,  o);
            s2 += __shfl_xor_sync(0xffffffffu, s2, o);
        }
        float m   = s * (1.0f / 64.0f);
        float var = s2 * (1.0f / 64.0f) - m * m;
        float rs  = rsqrtf(var + 1e-5f);
        aT[o0 + t]      = (v0 - m) * rs * gv.x + bv.x;
        aT[o0 + 10 + t] = (v1 - m) * rs * gv.y + bv.y;
    }
}

extern "C" __global__ void __launch_bounds__(WPB * 32, 2)
wt49_kernel(const float* __restrict__ x,
            const float* __restrict__ embed_w, const float* __restrict__ embed_b,
            const float* __restrict__ ln1_g,   const float* __restrict__ ln1_b,
            const float* __restrict__ qkv_w,   const float* __restrict__ proj_w,
            const float* __restrict__ ln2_g,   const float* __restrict__ ln2_b,
            const float* __restrict__ ffn_w1,  const float* __restrict__ ffn_b1,
            const float* __restrict__ ffn_w2,  const float* __restrict__ ffn_b2,
            const float* __restrict__ lnf_g,   const float* __restrict__ lnf_b,
            const float* __restrict__ head_w,  const float* __restrict__ head_b,
            float* __restrict__ out, int nB)
{
    extern __shared__ char smem_raw[];
    const int wid  = threadIdx.x >> 5;
    const int l    = threadIdx.x & 31;
    const int b    = blockIdx.x * WPB + wid;
    if (b >= nB) return;                      // warp-uniform; only __syncwarp used below

    char* wb = smem_raw + wid * PER_WARP_SMEM;
    float* s_h  = reinterpret_cast<float*>(wb);
    float* s_aT = reinterpret_cast<float*>(wb + S_AT);
    float* s_zT = reinterpret_cast<float*>(wb + S_ZT);
    float* s_qk = reinterpret_cast<float*>(wb + S_QK);
    float* s_att = s_aT;                      // raw scores alias (post-qkv, pre-y)
    float* s_atT = s_zT;                      // raw attT alias (pre-FFN)

    const int half = l >> 4;                  // split-K half
    const int lq   = l & 15;
    const int cb   = lq * 4;                  // 4 output cols per lane
    const int c0   = l * 2;                   // C=2 layout for LN/head
    const unsigned FULL = 0xffffffffu;

    // ---------------- embed: h = x @ We + be ----------------
    {
        float4 xv = make_float4(0.f, 0.f, 0.f, 0.f);
        if (l < TT) xv = *reinterpret_cast<const float4*>(x + (size_t)b * 40 + l * 4);
        float4 e0 = *reinterpret_cast<const float4*>(embed_w + 0 * DD + cb);
        float4 e1 = *reinterpret_cast<const float4*>(embed_w + 1 * DD + cb);
        float4 e2 = *reinterpret_cast<const float4*>(embed_w + 2 * DD + cb);
        float4 e3 = *reinterpret_cast<const float4*>(embed_w + 3 * DD + cb);
        float4 eb = *reinterpret_cast<const float4*>(embed_b + cb);
        #pragma unroll
        for (int t = 0; t < TT; t++) {
            float a0 = __shfl_sync(FULL, xv.x, t);
            float a1 = __shfl_sync(FULL, xv.y, t);
            float a2 = __shfl_sync(FULL, xv.z, t);
            float a3 = __shfl_sync(FULL, xv.w, t);
            float4 r;
            r.x = fmaf(a3, e3.x, fmaf(a2, e2.x, fmaf(a1, e1.x, fmaf(a0, e0.x, eb.x))));
            r.y = fmaf(a3, e3.y, fmaf(a2, e2.y, fmaf(a1, e1.y, fmaf(a0, e0.y, eb.y))));
            r.z = fmaf(a3, e3.z, fmaf(a2, e2.z, fmaf(a1, e1.z, fmaf(a0, e0.z, eb.z))));
            r.w = fmaf(a3, e3.w, fmaf(a2, e2.w, fmaf(a1, e1.w, fmaf(a0, e0.w, eb.w))));
            if ((t & 1) == half)
                *reinterpret_cast<float4*>(s_h + t * DD + cb) = r;
        }
    }
    __syncwarp();

    u64 vacc[4][5];   // v of current layer, kept in registers

    // ---------------- transformer layers ----------------
    #pragma unroll 1
    for (int li = 0; li < NL; li++) {
        // LN1 -> s_aT
        layernorm_T(s_h, ln1_g + li * DD, ln1_b + li * DD, s_aT, c0);
        __syncwarp();

        // qkv
        const float* Wq = qkv_w + (size_t)li * (DD * 3 * DD);
        {
            u64 acc[4][5]; zero_acc(acc);
            gemm_sk<64>(Wq, 192, s_aT, half, cb, acc);
            reduce_sk(acc);
            store_rows(s_qk, 128, acc, half, cb);               // q -> cols 0..63
        }
        {
            u64 acc[4][5]; zero_acc(acc);
            gemm_sk<64>(Wq + 64, 192, s_aT, half, cb, acc);
            reduce_sk(acc);
            store_rows(s_qk + 64, 128, acc, half, cb);          // k -> cols 64..127
        }
        zero_acc(vacc);
        gemm_sk<64>(Wq + 128, 192, s_aT, half, cb, vacc);
        reduce_sk(vacc);                                        // v stays in regs
        __syncwarp();

        // scores: att[hh][tq][tk] = 0.25 * dot(q,k)
        #pragma unroll 1
        for (int idx = l; idx < 400; idx += 32) {
            int hh = idx / 100;
            int r  = idx % 100;
            int tq = r / 10, tk = r % 10;
            const float* qp = s_qk + tq * 128 + hh * 16;
            const float* kp = s_qk + tk * 128 + 64 + hh * 16;
            float dot = 0.f;
            #pragma unroll
            for (int j = 0; j < 16; j += 4) {
                float4 q4 = *reinterpret_cast<const float4*>(qp + j);
                float4 k4 = *reinterpret_cast<const float4*>(kp + j);
                dot += q4.x * k4.x + q4.y * k4.y + q4.z * k4.z + q4.w * k4.w;
            }
            s_att[idx] = dot * 0.25f;
        }
        __syncwarp();

        // causal softmax -> transposed attT[hh][tk][tq] in s_zT
        #pragma unroll 1
        for (int r = l; r < 40; r += 32) {
            int hh = r / 10, tq = r % 10;
            const float* row = s_att + r * 10;
            float v[TT];
            #pragma unroll
            for (int k = 0; k < TT; k++) v[k] = row[k];
            float m = v[0];
            for (int k = 1; k <= tq; k++) m = fmaxf(m, v[k]);
            float ssum = 0.f;
            for (int k = 0; k <= tq; k++) { float e = expf(v[k] - m); v[k] = e; ssum += e; }
            float inv = 1.f / ssum;
            #pragma unroll
            for (int k = 0; k < TT; k++)
                s_atT[hh * 100 + k * 10 + tq] = (k <= tq) ? v[k] * inv : 0.f;
        }
        __syncwarp();

        // y = att @ v  (v in regs; both halves compute full y), write yT -> s_aT
        {
            const int hh = cb >> 4;
            const float* at = s_atT + hh * 100;
            u64 y[4][5]; zero_acc(y);
            #pragma unroll
            for (int tk = 0; tk < TT; tk++) {
                u64 ap[5];
                #pragma unroll
                for (int tp = 0; tp < 5; tp++)
                    ap[tp] = *reinterpret_cast<const u64*>(at + tk * 10 + 2 * tp);
                #pragma unroll
                for (int j = 0; j < 4; j++) {
                    float a0, a1; up2(vacc[j][tk >> 1], a0, a1);
                    u64 dv = dup1((tk & 1) ? a1 : a0);
                    #pragma unroll
                    for (int tp = 0; tp < 5; tp++) y[j][tp] = ffma2(ap[tp], dv, y[j][tp]);
                }
            }
            #pragma unroll
            for (int tp = 0; tp < 5; tp++) if ((tp & 1) == half)
                #pragma unroll
                for (int j = 0; j < 4; j++)
                    *reinterpret_cast<u64*>(s_aT + at_off(cb + j) + 2 * tp) = y[j][tp];
        }
        __syncwarp();

        // h += y @ Wproj
        {
            u64 acc[4][5]; zero_acc(acc);
            gemm_sk<64>(proj_w + (size_t)li * DD * DD, 64, s_aT, half, cb, acc);
            reduce_sk(acc);
            rmw_h(s_h, acc, half, cb);
        }
        __syncwarp();

        // LN2 -> s_aT
        layernorm_T(s_h, ln2_g + li * DD, ln2_b + li * DD, s_aT, c0);
        __syncwarp();

        // FFN: h += gelu(hn @ W1 + b1) @ W2 + b2, 4 chunks of 64 hidden cols
        {
            const float* W1 = ffn_w1 + (size_t)li * DD * 256;
            const float* W2 = ffn_w2 + (size_t)li * 256 * DD;
            const float* B1 = ffn_b1 + li * 256;
            #pragma unroll 1
            for (int cc = 0; cc < 4; cc++) {
                u64 zacc[4][5];
                {
                    float4 b1v = *reinterpret_cast<const float4*>(B1 + cc * 64 + cb);
                    u64 i0 = half ? 0ull : dup1(b1v.x);
                    u64 i1 = half ? 0ull : dup1(b1v.y);
                    u64 i2 = half ? 0ull : dup1(b1v.z);
                    u64 i3 = half ? 0ull : dup1(b1v.w);
                    #pragma unroll
                    for (int tp = 0; tp < 5; tp++) {
                        zacc[0][tp] = i0; zacc[1][tp] = i1; zacc[2][tp] = i2; zacc[3][tp] = i3;
                    }
                }
                gemm_sk<64>(W1 + cc * 64, 256, s_aT, half, cb, zacc);
                reduce_sk(zacc);
                #pragma unroll
                for (int tp = 0; tp < 5; tp++) if ((tp & 1) == half)
                    #pragma unroll
                    for (int j = 0; j < 4; j++) {
                        float zl, zh; up2(zacc[j][tp], zl, zh);
                        *reinterpret_cast<u64*>(s_zT + at_off(cb + j) + 2 * tp) =
                            pk2(gelu_exact(zl), gelu_exact(zh));
                    }
                __syncwarp();
                u64 wacc[4][5];
                if (cc == 0) {
                    float4 b2v = *reinterpret_cast<const float4*>(ffn_b2 + li * DD + cb);
                    u64 i0 = half ? 0ull : dup1(b2v.x);
                    u64 i1 = half ? 0ull : dup1(b2v.y);
                    u64 i2 = half ? 0ull : dup1(b2v.z);
                    u64 i3 = half ? 0ull : dup1(b2v.w);
                    #pragma unroll
                    for (int tp = 0; tp < 5; tp++) {
                        wacc[0][tp] = i0; wacc[1][tp] = i1; wacc[2][tp] = i2; wacc[3][tp] = i3;
                    }
                } else {
                    zero_acc(wacc);
                }
                gemm_sk<64>(W2 + (size_t)(cc * 64) * DD, 64, s_zT, half, cb, wacc);
                reduce_sk(wacc);
                rmw_h(s_h, wacc, half, cb);
                __syncwarp();
            }
        }
    }

    // ---------------- final LN (t=9) + head ----------------
    {
        float v0 = s_h[9 * DD + c0], v1 = s_h[9 * DD + c0 + 1];
        float s = v0 + v1, s2 = v0 * v0 + v1 * v1;
        #pragma unroll
        for (int o = 16; o > 0; o >>= 1) {
            s  += __shfl_xor_sync(FULL, s,  o);
            s2 += __shfl_xor_sync(FULL, s2, o);
        }
        float m   = s * (1.0f / 64.0f);
        float var = s2 * (1.0f / 64.0f) - m * m;
        float rs  = rsqrtf(var + 1e-5f);
        float2 gv = *reinterpret_cast<const float2*>(lnf_g + c0);
        float2 bv = *reinterpret_cast<const float2*>(lnf_b + c0);
        s_qk[c0]     = (v0 - m) * rs * gv.x + bv.x;
        s_qk[c0 + 1] = (v1 - m) * rs * gv.y + bv.y;
    }
    __syncwarp();
    if (l < 10) {
        float acc = head_b[l];
        #pragma unroll 1
        for (int d = 0; d < DD; d++) acc = fmaf(s_qk[d], head_w[d * 10 + l], acc);
        out[(size_t)b * 10 + l] = acc;
    }
}

extern "C" void kernel_launch(void* const* d_in, const int* in_sizes, int n_in,
                              void* d_out, int out_size)
{
    const float* x       = (const float*)d_in[0];
    const float* embed_w = (const float*)d_in[1];
    const float* embed_b = (const float*)d_in[2];
    const float* ln1_g   = (const float*)d_in[3];
    const float* ln1_b   = (const float*)d_in[4];
    const float* qkv_w   = (const float*)d_in[5];
    const float* proj_w  = (const float*)d_in[6];
    const float* ln2_g   = (const float*)d_in[7];
    const float* ln2_b   = (const float*)d_in[8];
    const float* ffn_w1  = (const float*)d_in[9];
    const float* ffn_b1  = (const float*)d_in[10];
    const float* ffn_w2  = (const float*)d_in[11];
    const float* ffn_b2  = (const float*)d_in[12];
    const float* lnf_g   = (const float*)d_in[13];
    const float* lnf_b   = (const float*)d_in[14];
    const float* head_w  = (const float*)d_in[15];
    const float* head_b  = (const float*)d_in[16];
    float* out = (float*)d_out;

    int nB = in_sizes[0] / 40;                        // [B, T=10, 4]
    int grid = (nB + WPB - 1) / WPB;
    size_t smem = (size_t)WPB * PER_WARP_SMEM;        // 102912 B -> 2 blocks/SM

    cudaFuncSetAttribute(wt49_kernel, cudaFuncAttributeMaxDynamicSharedMemorySize, (int)smem);

    wt49_kernel<<<grid, WPB * 32, smem>>>(x, embed_w, embed_b, ln1_g, ln1_b, qkv_w, proj_w,
                                          ln2_g, ln2_b, ffn_w1, ffn_b1, ffn_w2, ffn_b2,
                                          lnf_g, lnf_b, head_w, head_b, out, nB);
}

// round 11
// speedup vs baseline: 1.6160x; 1.1902x over previous
#include <cuda_runtime.h>
#include <math.h>

typedef unsigned long long u64;

#define TT 10
#define DD 64
#define NL 3
#define WPB 10
// per-warp smem layout (bytes):
//   s_h @0     [10][64] f32 residual              2560
//   A   @2560  padded transposed buf (2x324 f)    2592   (aT / vT / yT)
//   B   @5152  q rows [10][64] / attT / misc      2592
//   C   @7744  k rows [10][64] / z chunk (zT)     2592
#define OFF_A 2560
#define OFF_B 5152
#define OFF_C 7744
#define PER_WARP_SMEM 10336
#define ATH 324   // half-stride of padded transposed buffers, floats (32*10 + 4 pad)

// ---------- packed f32x2 helpers ----------
__device__ __forceinline__ u64 pk2(float x, float y) {
    u64 r; asm("mov.b64 %0, {%1, %2};" : "=l"(r) : "f"(x), "f"(y)); return r;
}
__device__ __forceinline__ u64 dup1(float x) { return pk2(x, x); }
__device__ __forceinline__ void up2(u64 v, float& x, float& y) {
    asm("mov.b64 {%0, %1}, %2;" : "=f"(x), "=f"(y) : "l"(v));
}
__device__ __forceinline__ u64 ffma2(u64 a, u64 b, u64 c) {
    u64 d; asm("fma.rn.f32x2 %0, %1, %2, %3;" : "=l"(d) : "l"(a), "l"(b), "l"(c)); return d;
}
__device__ __forceinline__ u64 add2(u64 a, u64 b) {
    u64 c; asm("add.rn.f32x2 %0, %1, %2;" : "=l"(c) : "l"(a), "l"(b)); return c;
}
__device__ __forceinline__ float gelu_exact(float x) {
    return 0.5f * x * (1.0f + erff(x * 0.7071067811865475f));
}
__device__ __forceinline__ int at_off(int c) {
    return ((c >> 5) * ATH) + ((c & 31) * 10);
}

// ---------- split-K C=4 gemm ----------
template<int KK>
__device__ __forceinline__ void gemm_sk(const float* __restrict__ w, const int ldw,
                                        const float* __restrict__ aT,
                                        const int half, const int cb, u64 acc[4][5])
{
    const float* a  = aT + half * ATH;
    const float* wp = w + (half * (KK / 2)) * ldw + cb;
    #pragma unroll 2
    for (int kk = 0; kk < KK / 2; kk += 2) {
        const ulonglong2* ap = reinterpret_cast<const ulonglong2*>(a + kk * 10);
        ulonglong2 p0 = ap[0], p1 = ap[1], p2 = ap[2], p3 = ap[3], p4 = ap[4];
        float4 w0 = *reinterpret_cast<const float4*>(wp + kk * ldw);
        float4 w1 = *reinterpret_cast<const float4*>(wp + (kk + 1) * ldw);
        u64 d0[4] = { dup1(w0.x), dup1(w0.y), dup1(w0.z), dup1(w0.w) };
        u64 d1[4] = { dup1(w1.x), dup1(w1.y), dup1(w1.z), dup1(w1.w) };
        u64 avA[5] = { p0.x, p0.y, p1.x, p1.y, p2.x };
        u64 avB[5] = { p2.y, p3.x, p3.y, p4.x, p4.y };
        #pragma unroll
        for (int tp = 0; tp < 5; tp++)
            #pragma unroll
            for (int j = 0; j < 4; j++)
                acc[j][tp] = ffma2(avA[tp], d0[j], acc[j][tp]);
        #pragma unroll
        for (int tp = 0; tp < 5; tp++)
            #pragma unroll
            for (int j = 0; j < 4; j++)
                acc[j][tp] = ffma2(avB[tp], d1[j], acc[j][tp]);
    }
}

__device__ __forceinline__ void reduce_sk(u64 acc[4][5]) {
    #pragma unroll
    for (int j = 0; j < 4; j++)
        #pragma unroll
        for (int tp = 0; tp < 5; tp++) {
            u64 o = __shfl_xor_sync(0xffffffffu, acc[j][tp], 16);
            acc[j][tp] = add2(acc[j][tp], o);
        }
}

__device__ __forceinline__ void zero_acc(u64 acc[4][5]) {
    #pragma unroll
    for (int j = 0; j < 4; j++)
        #pragma unroll
        for (int tp = 0; tp < 5; tp++) acc[j][tp] = 0ull;
}

// store reduced acc into row-major dst [t][col], stride ldd; tp split by half parity
__device__ __forceinline__ void store_rows(float* __restrict__ dst, const int ldd,
                                           u64 acc[4][5], const int half, const int cb)
{
    #pragma unroll
    for (int tp = 0; tp < 5; tp++) if ((tp & 1) == half) {
        float l0,h0,l1,h1,l2,h2,l3,h3;
        up2(acc[0][tp], l0, h0); up2(acc[1][tp], l1, h1);
        up2(acc[2][tp], l2, h2); up2(acc[3][tp], l3, h3);
        *reinterpret_cast<float4*>(dst + (2*tp    ) * ldd + cb) = make_float4(l0,l1,l2,l3);
        *reinterpret_cast<float4*>(dst + (2*tp + 1) * ldd + cb) = make_float4(h0,h1,h2,h3);
    }
}

// store reduced acc transposed into padded-T buffer; tp split by half parity
__device__ __forceinline__ void store_T(float* __restrict__ dst, u64 acc[4][5],
                                        const int half, const int cb)
{
    #pragma unroll
    for (int tp = 0; tp < 5; tp++) if ((tp & 1) == half)
        #pragma unroll
        for (int j = 0; j < 4; j++)
            *reinterpret_cast<u64*>(dst + at_off(cb + j) + 2 * tp) = acc[j][tp];
}

// h[t][cb..cb+3] += acc  (tp split by half parity)
__device__ __forceinline__ void rmw_h(float* __restrict__ s_h, u64 acc[4][5],
                                      const int half, const int cb)
{
    #pragma unroll
    for (int tp = 0; tp < 5; tp++) if ((tp & 1) == half) {
        float l0,h0,l1,h1,l2,h2,l3,h3;
        up2(acc[0][tp], l0, h0); up2(acc[1][tp], l1, h1);
        up2(acc[2][tp], l2, h2); up2(acc[3][tp], l3, h3);
        float4* p0 = reinterpret_cast<float4*>(s_h + (2*tp) * DD + cb);
        float4 v0 = *p0; v0.x += l0; v0.y += l1; v0.z += l2; v0.w += l3; *p0 = v0;
        float4* p1 = reinterpret_cast<float4*>(s_h + (2*tp + 1) * DD + cb);
        float4 v1 = *p1; v1.x += h0; v1.y += h1; v1.z += h2; v1.w += h3; *p1 = v1;
    }
}

// LayerNorm over D=64 from s_h; lane handles cols c0=2l, c0+1; writes padded transposed aT.
__device__ __forceinline__ void layernorm_T(const float* __restrict__ s_h,
                                            const float* __restrict__ g,
                                            const float* __restrict__ bb,
                                            float* __restrict__ aT, const int c0)
{
    float2 gv = *reinterpret_cast<const float2*>(g + c0);
    float2 bv = *reinterpret_cast<const float2*>(bb + c0);
    const int o0 = at_off(c0);
    #pragma unroll
    for (int t = 0; t < TT; t++) {
        float v0 = s_h[t * DD + c0], v1 = s_h[t * DD + c0 + 1];
        float s = v0 + v1, s2 = v0 * v0 + v1 * v1;
        #pragma unroll
        for (int o = 16; o > 0; o >>= 1) {
            s  += __shfl_xor_sync(0xffffffffu, s,  o);
            s2 += __shfl_xor_sync(0xffffffffu, s2, o);
        }
        float m   = s * (1.0f / 64.0f);
        float var = s2 * (1.0f / 64.0f) - m * m;
        float rs  = rsqrtf(var + 1e-5f);
        aT[o0 + t]      = (v0 - m) * rs * gv.x + bv.x;
        aT[o0 + 10 + t] = (v1 - m) * rs * gv.y + bv.y;
    }
}

// fused causal scores + softmax for one (hh, tq) row; q in B rows, k in C rows.
// Returns att row (10 floats, masked entries 0).
__device__ __forceinline__ void score_row(const float* __restrict__ Bq,
                                          const float* __restrict__ Ck,
                                          const int hh, const int tq,
                                          float* __restrict__ rowv)
{
    const ulonglong2* qp = reinterpret_cast<const ulonglong2*>(Bq + tq * 64 + hh * 16);
    ulonglong2 q0 = qp[0], q1 = qp[1], q2 = qp[2], q3 = qp[3];
    float mx = -1e30f;
    #pragma unroll
    for (int tk = 0; tk < TT; tk++) {
        float d = 0.f;
        if (tk <= tq) {
            const ulonglong2* kp = reinterpret_cast<const ulonglong2*>(Ck + tk * 64 + hh * 16);
            ulonglong2 k0 = kp[0], k1 = kp[1], k2 = kp[2], k3 = kp[3];
            u64 a = ffma2(q0.x, k0.x, 0ull);
            a = ffma2(q0.y, k0.y, a);
            a = ffma2(q1.x, k1.x, a);
            a = ffma2(q1.y, k1.y, a);
            a = ffma2(q2.x, k2.x, a);
            a = ffma2(q2.y, k2.y, a);
            a = ffma2(q3.x, k3.x, a);
            a = ffma2(q3.y, k3.y, a);
            float lo, hi; up2(a, lo, hi);
            d = (lo + hi) * 0.25f;
            mx = fmaxf(mx, d);
        }
        rowv[tk] = d;
    }
    float ss = 0.f;
    #pragma unroll
    for (int tk = 0; tk < TT; tk++) {
        if (tk <= tq) { float e = __expf(rowv[tk] - mx); rowv[tk] = e; ss += e; }
    }
    float inv = 1.f / ss;
    #pragma unroll
    for (int tk = 0; tk < TT; tk++)
        rowv[tk] = (tk <= tq) ? rowv[tk] * inv : 0.f;
}

extern "C" __global__ void __launch_bounds__(WPB * 32, 2)
wt49_kernel(const float* __restrict__ x,
            const float* __restrict__ embed_w, const float* __restrict__ embed_b,
            const float* __restrict__ ln1_g,   const float* __restrict__ ln1_b,
            const float* __restrict__ qkv_w,   const float* __restrict__ proj_w,
            const float* __restrict__ ln2_g,   const float* __restrict__ ln2_b,
            const float* __restrict__ ffn_w1,  const float* __restrict__ ffn_b1,
            const float* __restrict__ ffn_w2,  const float* __restrict__ ffn_b2,
            const float* __restrict__ lnf_g,   const float* __restrict__ lnf_b,
            const float* __restrict__ head_w,  const float* __restrict__ head_b,
            float* __restrict__ out, int nB)
{
    extern __shared__ char smem_raw[];
    const int wid  = threadIdx.x >> 5;
    const int l    = threadIdx.x & 31;
    const int b    = blockIdx.x * WPB + wid;
    if (b >= nB) return;                      // warp-uniform; only __syncwarp used below

    char* wb = smem_raw + wid * PER_WARP_SMEM;
    float* s_h = reinterpret_cast<float*>(wb);
    float* A   = reinterpret_cast<float*>(wb + OFF_A);
    float* Bq  = reinterpret_cast<float*>(wb + OFF_B);
    float* Ck  = reinterpret_cast<float*>(wb + OFF_C);

    const int half = l >> 4;
    const int lq   = l & 15;
    const int cb   = lq * 4;
    const int hh   = lq >> 2;                 // head for y-step (cb/16)
    const int c0   = l * 2;
    const unsigned FULL = 0xffffffffu;

    // ---------------- embed: h = x @ We + be ----------------
    {
        float4 xv = make_float4(0.f, 0.f, 0.f, 0.f);
        if (l < TT) xv = *reinterpret_cast<const float4*>(x + (size_t)b * 40 + l * 4);
        float4 e0 = *reinterpret_cast<const float4*>(embed_w + 0 * DD + cb);
        float4 e1 = *reinterpret_cast<const float4*>(embed_w + 1 * DD + cb);
        float4 e2 = *reinterpret_cast<const float4*>(embed_w + 2 * DD + cb);
        float4 e3 = *reinterpret_cast<const float4*>(embed_w + 3 * DD + cb);
        float4 eb = *reinterpret_cast<const float4*>(embed_b + cb);
        #pragma unroll
        for (int t = 0; t < TT; t++) {
            float a0 = __shfl_sync(FULL, xv.x, t);
            float a1 = __shfl_sync(FULL, xv.y, t);
            float a2 = __shfl_sync(FULL, xv.z, t);
            float a3 = __shfl_sync(FULL, xv.w, t);
            float4 r;
            r.x = fmaf(a3, e3.x, fmaf(a2, e2.x, fmaf(a1, e1.x, fmaf(a0, e0.x, eb.x))));
            r.y = fmaf(a3, e3.y, fmaf(a2, e2.y, fmaf(a1, e1.y, fmaf(a0, e0.y, eb.y))));
            r.z = fmaf(a3, e3.z, fmaf(a2, e2.z, fmaf(a1, e1.z, fmaf(a0, e0.z, eb.z))));
            r.w = fmaf(a3, e3.w, fmaf(a2, e2.w, fmaf(a1, e1.w, fmaf(a0, e0.w, eb.w))));
            if ((t & 1) == half)
                *reinterpret_cast<float4*>(s_h + t * DD + cb) = r;
        }
    }
    __syncwarp();

    // ---------------- transformer layers ----------------
    #pragma unroll 1
    for (int li = 0; li < NL; li++) {
        // LN1 -> A (transposed)
        layernorm_T(s_h, ln1_g + li * DD, ln1_b + li * DD, A, c0);
        __syncwarp();

        const float* Wq = qkv_w + (size_t)li * (DD * 3 * DD);
        // q -> B rows
        {
            u64 acc[4][5]; zero_acc(acc);
            gemm_sk<64>(Wq, 192, A, half, cb, acc);
            reduce_sk(acc);
            store_rows(Bq, 64, acc, half, cb);
        }
        // k -> C rows
        {
            u64 acc[4][5]; zero_acc(acc);
            gemm_sk<64>(Wq + 64, 192, A, half, cb, acc);
            reduce_sk(acc);
            store_rows(Ck, 64, acc, half, cb);
        }
        // v -> regs, then spill transposed into A (A dead after this gemm)
        {
            u64 vacc[4][5]; zero_acc(vacc);
            gemm_sk<64>(Wq + 128, 192, A, half, cb, vacc);
            reduce_sk(vacc);
            __syncwarp();                 // all lanes done READING A before overwrite
            store_T(A, vacc, half, cb);   // vT -> A
        }
        __syncwarp();

        // fused causal scores + softmax; rows balanced: lane l -> row l, and (l<8) -> row 39-l
        float rowA[TT], rowB[TT];
        {
            int ra = l;                       // 0..31
            score_row(Bq, Ck, ra / 10, ra % 10, rowA);
            if (l < 8) {
                int rb = 39 - l;              // 32..39
                score_row(Bq, Ck, rb / 10, rb % 10, rowB);
            }
        }
        __syncwarp();                         // all q/k reads done before attT overwrites B
        {
            int ra = l, ha = ra / 10, tqa = ra % 10;
            #pragma unroll
            for (int tk = 0; tk < TT; tk++)
                Bq[ha * 100 + tk * 10 + tqa] = rowA[tk];
            if (l < 8) {
                int rb = 39 - l, hb = rb / 10, tqb = rb % 10;
                #pragma unroll
                for (int tk = 0; tk < TT; tk++)
                    Bq[hb * 100 + tk * 10 + tqb] = rowB[tk];
            }
        }
        __syncwarp();

        // y = att @ v : private vT loads from A, broadcast attT from B, yT -> A
        {
            u64 vreg[4][5];
            #pragma unroll
            for (int j = 0; j < 4; j++)
                #pragma unroll
                for (int tp = 0; tp < 5; tp++)
                    vreg[j][tp] = *reinterpret_cast<const u64*>(A + at_off(cb + j) + 2 * tp);
            __syncwarp();                     // all vT reads done before yT overwrite
            const float* at = Bq + hh * 100;
            u64 y[4][5]; zero_acc(y);
            #pragma unroll
            for (int tk = 0; tk < TT; tk++) {
                u64 ap[5];
                #pragma unroll
                for (int tp = 0; tp < 5; tp++)
                    ap[tp] = *reinterpret_cast<const u64*>(at + tk * 10 + 2 * tp);
                #pragma unroll
                for (int j = 0; j < 4; j++) {
                    float a0, a1; up2(vreg[j][tk >> 1], a0, a1);
                    u64 dv = dup1((tk & 1) ? a1 : a0);
                    #pragma unroll
                    for (int tp = 0; tp < 5; tp++) y[j][tp] = ffma2(ap[tp], dv, y[j][tp]);
                }
            }
            #pragma unroll
            for (int tp = 0; tp < 5; tp++) if ((tp & 1) == half)
                #pragma unroll
                for (int j = 0; j < 4; j++)
                    *reinterpret_cast<u64*>(A + at_off(cb + j) + 2 * tp) = y[j][tp];
        }
        __syncwarp();

        // h += y @ Wproj
        {
            u64 acc[4][5]; zero_acc(acc);
            gemm_sk<64>(proj_w + (size_t)li * DD * DD, 64, A, half, cb, acc);
            reduce_sk(acc);
            rmw_h(s_h, acc, half, cb);
        }
        __syncwarp();

        // LN2 -> A
        layernorm_T(s_h, ln2_g + li * DD, ln2_b + li * DD, A, c0);
        __syncwarp();

        // FFN: h += gelu(hn @ W1 + b1) @ W2 + b2, 4 chunks of 64 hidden; z chunk in C
        {
            const float* W1 = ffn_w1 + (size_t)li * DD * 256;
            const float* W2 = ffn_w2 + (size_t)li * 256 * DD;
            const float* B1 = ffn_b1 + li * 256;
            #pragma unroll 1
            for (int cc = 0; cc < 4; cc++) {
                u64 zacc[4][5];
                {
                    float4 b1v = *reinterpret_cast<const float4*>(B1 + cc * 64 + cb);
                    u64 i0 = half ? 0ull : dup1(b1v.x);
                    u64 i1 = half ? 0ull : dup1(b1v.y);
                    u64 i2 = half ? 0ull : dup1(b1v.z);
                    u64 i3 = half ? 0ull : dup1(b1v.w);
                    #pragma unroll
                    for (int tp = 0; tp < 5; tp++) {
                        zacc[0][tp] = i0; zacc[1][tp] = i1; zacc[2][tp] = i2; zacc[3][tp] = i3;
                    }
                }
                gemm_sk<64>(W1 + cc * 64, 256, A, half, cb, zacc);
                reduce_sk(zacc);
                #pragma unroll
                for (int tp = 0; tp < 5; tp++) if ((tp & 1) == half)
                    #pragma unroll
                    for (int j = 0; j < 4; j++) {
                        float zl, zh; up2(zacc[j][tp], zl, zh);
                        *reinterpret_cast<u64*>(Ck + at_off(cb + j) + 2 * tp) =
                            pk2(gelu_exact(zl), gelu_exact(zh));
                    }
                __syncwarp();
                u64 wacc[4][5];
                if (cc == 0) {
                    float4 b2v = *reinterpret_cast<const float4*>(ffn_b2 + li * DD + cb);
                    u64 i0 = half ? 0ull : dup1(b2v.x);
                    u64 i1 = half ? 0ull : dup1(b2v.y);
                    u64 i2 = half ? 0ull : dup1(b2v.z);
                    u64 i3 = half ? 0ull : dup1(b2v.w);
                    #pragma unroll
                    for (int tp = 0; tp < 5; tp++) {
                        wacc[0][tp] = i0; wacc[1][tp] = i1; wacc[2][tp] = i2; wacc[3][tp] = i3;
                    }
                } else {
                    zero_acc(wacc);
                }
                gemm_sk<64>(W2 + (size_t)(cc * 64) * DD, 64, Ck, half, cb, wacc);
                reduce_sk(wacc);
                rmw_h(s_h, wacc, half, cb);
                __syncwarp();
            }
        }
    }

    // ---------------- final LN (t=9) + head ----------------
    {
        float v0 = s_h[9 * DD + c0], v1 = s_h[9 * DD + c0 + 1];
        float s = v0 + v1, s2 = v0 * v0 + v1 * v1;
        #pragma unroll
        for (int o = 16; o > 0; o >>= 1) {
            s  += __shfl_xor_sync(FULL, s,  o);
            s2 += __shfl_xor_sync(FULL, s2, o);
        }
        float m   = s * (1.0f / 64.0f);
        float var = s2 * (1.0f / 64.0f) - m * m;
        float rs  = rsqrtf(var + 1e-5f);
        float2 gv = *reinterpret_cast<const float2*>(lnf_g + c0);
        float2 bv = *reinterpret_cast<const float2*>(lnf_b + c0);
        Bq[c0]     = (v0 - m) * rs * gv.x + bv.x;
        Bq[c0 + 1] = (v1 - m) * rs * gv.y + bv.y;
    }
    __syncwarp();
    if (l < 10) {
        float acc = head_b[l];
        #pragma unroll 1
        for (int d = 0; d < DD; d++) acc = fmaf(Bq[d], head_w[d * 10 + l], acc);
        out[(size_t)b * 10 + l] = acc;
    }
}

extern "C" void kernel_launch(void* const* d_in, const int* in_sizes, int n_in,
                              void* d_out, int out_size)
{
    const float* x       = (const float*)d_in[0];
    const float* embed_w = (const float*)d_in[1];
    const float* embed_b = (const float*)d_in[2];
    const float* ln1_g   = (const float*)d_in[3];
    const float* ln1_b   = (const float*)d_in[4];
    const float* qkv_w   = (const float*)d_in[5];
    const float* proj_w  = (const float*)d_in[6];
    const float* ln2_g   = (const float*)d_in[7];
    const float* ln2_b   = (const float*)d_in[8];
    const float* ffn_w1  = (const float*)d_in[9];
    const float* ffn_b1  = (const float*)d_in[10];
    const float* ffn_w2  = (const float*)d_in[11];
    const float* ffn_b2  = (const float*)d_in[12];
    const float* lnf_g   = (const float*)d_in[13];
    const float* lnf_b   = (const float*)d_in[14];
    const float* head_w  = (const float*)d_in[15];
    const float* head_b  = (const float*)d_in[16];
    float* out = (float*)d_out;

    int nB = in_sizes[0] / 40;                        // [B, T=10, 4]
    int grid = (nB + WPB - 1) / WPB;
    size_t smem = (size_t)WPB * PER_WARP_SMEM;        // 103360 B -> 2 blocks/SM

    cudaFuncSetAttribute(wt49_kernel, cudaFuncAttributeMaxDynamicSharedMemorySize, (int)smem);

    wt49_kernel<<<grid, WPB * 32, smem>>>(x, embed_w, embed_b, ln1_g, ln1_b, qkv_w, proj_w,
                                          ln2_g, ln2_b, ffn_w1, ffn_b1, ffn_w2, ffn_b2,
                                          lnf_g, lnf_b, head_w, head_b, out, nB);
}